// round 8
// baseline (speedup 1.0000x reference)
#include <cuda_runtime.h>

// ---------------------------------------------------------------------------
// yolo_detect_target — coalesced 2-phase, batched loads, trimmed chain:
//  * full blocks (156/157) take a predication-free compile-time path
//  * boxes float4 loaded concurrently with phase-1 post loads (one latency
//    exposure, not two)
//  * release/acquire done-counter instead of __threadfence
//  * one fixed-point atomicAdd per block (deterministic: int adds commute)
// Rare paths (early conf break, row-0 fail -> global max) in last block only.
// ---------------------------------------------------------------------------

#define CONF_T   0.25f
#define THREADS  512
#define ROWS_PB  128
#define CPR      20                    // float4 chunks per row (C=80)
#define CHUNKS_PB (ROWS_PB * CPR)      // 2560 = 5 * 512
#define ITERS    (CHUNKS_PB / THREADS) // 5
#define FXSCALE  4294967296.0          // 2^32

__device__ unsigned long long g_fx         = 0ull;
__device__ int                g_first_fail = 0x7fffffff;
__device__ unsigned           g_done       = 0u;

__device__ __forceinline__ float warp_max(float m) {
    #pragma unroll
    for (int off = 16; off; off >>= 1)
        m = fmaxf(m, __shfl_xor_sync(0xffffffffu, m, off));
    return m;
}
__device__ __forceinline__ float warp_sum(float s) {
    #pragma unroll
    for (int off = 16; off; off >>= 1)
        s += __shfl_xor_sync(0xffffffffu, s, off);
    return s;
}

__device__ __forceinline__ unsigned done_add_release() {
    unsigned old;
    asm volatile("atom.release.gpu.global.add.u32 %0, [%1], 1;"
                 : "=r"(old) : "l"(&g_done) : "memory");
    return old;
}
__device__ __forceinline__ void acquire_fence() {
    asm volatile("fence.acquire.gpu;" ::: "memory");
}

__device__ __forceinline__ float row_max(const float* __restrict__ post,
                                         int row, int C) {
    float m = -3.4e38f;
    if (C == 80) {
        const float4* p = (const float4*)(post + (size_t)row * 80);
        #pragma unroll
        for (int i = 0; i < 20; i++) {
            float4 v = __ldg(p + i);
            m = fmaxf(m, fmaxf(fmaxf(v.x, v.y), fmaxf(v.z, v.w)));
        }
    } else {
        const float* p = post + (size_t)row * (size_t)C;
        for (int c = 0; c < C; c++) m = fmaxf(m, __ldg(p + c));
    }
    return m;
}

__global__ __launch_bounds__(THREADS)
void k_fused(const float* __restrict__ post,
             const float* __restrict__ boxes,
             int num, int C, long long total_elems,
             float* __restrict__ out)
{
    const int lane = threadIdx.x & 31;
    const int wid  = threadIdx.x >> 5;
    __shared__ float cmax[ROWS_PB * (CPR + 1)];   // pad 21: conflict-free
    __shared__ bool  sh_last;
    __shared__ float sh_red[THREADS / 32];

    const int r0 = blockIdx.x * ROWS_PB;
    int rows_here = num - r0;
    if (rows_here > ROWS_PB) rows_here = ROWS_PB;
    if (rows_here < 0) rows_here = 0;

    float val = 0.0f;

    if (C == 80) {
        const float4* p4 = (const float4*)post + (long long)r0 * CPR;
        // boxes load issued WITH phase-1 loads: one latency exposure
        float4 b = make_float4(0.f, 0.f, 0.f, 0.f);
        const bool has_row = (threadIdx.x < rows_here);
        if (has_row) b = __ldg((const float4*)boxes + (r0 + threadIdx.x));

        if (rows_here == ROWS_PB) {
            // ---------- full block: predication-free batched loads --------
            float4 v[ITERS];
            #pragma unroll
            for (int i = 0; i < ITERS; i++)
                v[i] = __ldg(p4 + (i * THREADS + threadIdx.x));
            #pragma unroll
            for (int i = 0; i < ITERS; i++) {
                int lc = i * THREADS + threadIdx.x;
                float m3 = fmaxf(fmaxf(v[i].x, v[i].y), fmaxf(v[i].z, v[i].w));
                int r = lc / CPR;
                int c = lc - r * CPR;
                cmax[r * (CPR + 1) + c] = m3;
            }
        } else {
            // ---------- partial tail block --------------------------------
            const int nchunks = rows_here * CPR;
            for (int lc = threadIdx.x; lc < nchunks; lc += THREADS) {
                float4 v = __ldg(p4 + lc);
                float m3 = fmaxf(fmaxf(v.x, v.y), fmaxf(v.z, v.w));
                int r = lc / CPR;
                int c = lc - r * CPR;
                cmax[r * (CPR + 1) + c] = m3;
            }
        }
        __syncthreads();

        // ---- phase 2: thread-per-row reduce from smem --------------------
        if (has_row) {
            const float* cm = &cmax[threadIdx.x * (CPR + 1)];
            float m = cm[0];
            #pragma unroll
            for (int c = 1; c < CPR; c++) m = fmaxf(m, cm[c]);
            val = m + ((b.x + b.y) + (b.z + b.w));
            if (!(m >= CONF_T)) atomicMin(&g_first_fail, r0 + threadIdx.x);
        }
    } else {
        // generic path (not hit for this shape)
        if (threadIdx.x < rows_here) {
            int row = r0 + threadIdx.x;
            float m = row_max(post, row, C);
            float4 b = __ldg((const float4*)boxes + row);
            val = m + ((b.x + b.y) + (b.z + b.w));
            if (!(m >= CONF_T)) atomicMin(&g_first_fail, row);
        }
    }

    // ---- block reduction -> one atomic ------------------------------------
    float s = warp_sum(val);
    if (lane == 0) sh_red[wid] = s;
    __syncthreads();
    if (wid == 0) {
        s = (lane < THREADS / 32) ? sh_red[lane] : 0.0f;
        s = warp_sum(s);
        if (lane == 0) {
            long long fx = __double2ll_rn((double)s * FXSCALE);
            atomicAdd(&g_fx, (unsigned long long)fx);
        }
    }
    __syncthreads();

    // ---- release done-counter (orders the g_fx add before the count) ------
    if (threadIdx.x == 0)
        sh_last = (done_add_release() == gridDim.x - 1);
    __syncthreads();
    if (!sh_last) return;
    acquire_fence();   // pairs with all blocks' releases

    // ================= last block: finalize ================================
    const int K = (g_first_fail < num) ? g_first_fail : num;

    if (K >= num) {
        if (threadIdx.x == 0)
            out[0] = (float)((double)(long long)g_fx / FXSCALE);
    } else if (K == 0) {
        // rare: row 0 failed -> loss = max over all of post
        float m = -3.4e38f;
        const long long n4 = total_elems >> 2;
        const float4* p4 = (const float4*)post;
        for (long long i = threadIdx.x; i < n4; i += THREADS) {
            float4 v = p4[i];
            m = fmaxf(m, fmaxf(fmaxf(v.x, v.y), fmaxf(v.z, v.w)));
        }
        for (long long i = (n4 << 2) + threadIdx.x; i < total_elems; i += THREADS)
            m = fmaxf(m, post[i]);
        m = warp_max(m);
        if (lane == 0) sh_red[wid] = m;
        __syncthreads();
        if (wid == 0) {
            m = (lane < THREADS / 32) ? sh_red[lane] : -3.4e38f;
            m = warp_max(m);
            if (lane == 0) out[0] = m;
        }
    } else {
        // rare: early break at K -> recompute sum over rows [0, K)
        float s2 = 0.0f;
        for (int r = threadIdx.x; r < K; r += THREADS) {
            float m = row_max(post, r, C);
            float4 b = __ldg((const float4*)boxes + r);
            s2 += m + ((b.x + b.y) + (b.z + b.w));
        }
        s2 = warp_sum(s2);
        __syncthreads();
        if (lane == 0) sh_red[wid] = s2;
        __syncthreads();
        if (wid == 0) {
            s2 = (lane < THREADS / 32) ? sh_red[lane] : 0.0f;
            s2 = warp_sum(s2);
            if (lane == 0) out[0] = s2;
        }
    }

    // ---- self-reset for next graph replay ---------------------------------
    __syncthreads();
    if (threadIdx.x == 0) {
        g_fx         = 0ull;
        g_first_fail = 0x7fffffff;
        g_done       = 0u;
    }
}

extern "C" void kernel_launch(void* const* d_in, const int* in_sizes, int n_in,
                              void* d_out, int out_size)
{
    const float* post  = (const float*)d_in[0];   // [N, C] fp32
    const float* boxes = (const float*)d_in[1];   // [N, 4] fp32
    const long long total = (long long)in_sizes[0];
    const int N = in_sizes[1] / 4;
    const int C = (int)(total / N);

    int num = (int)((double)N * 0.02);
    if (num < 1) num = 1;
    if (num > N) num = N;

    int blocks = (num + ROWS_PB - 1) / ROWS_PB;   // 157 for num=20000
    k_fused<<<blocks, THREADS>>>(post, boxes, num, C, total, (float*)d_out);
}

// round 9
// speedup vs baseline: 1.3223x; 1.3223x over previous
#include <cuda_runtime.h>

// ---------------------------------------------------------------------------
// yolo_detect_target — single kernel, single wave, fused sum+counter atomic.
// Per block: coalesced batched loads (MLP=6) -> per-chunk max -> smem ->
// thread-per-row max + box sum -> block sum -> ONE u64 atomicAdd that carries
// {counter(bit56+), biased fixed-point sum(low 56)}. The block that sees
// counter==grid-1 already holds the final total in-register: no re-read,
// no second atomic. Deterministic: integer adds commute; per-block fx is
// computed in a fixed order. Rare paths (early conf break, row-0 fail ->
// global max) run in the last block only.
// ---------------------------------------------------------------------------

#define CONF_T   0.25f
#define THREADS  512
#define ROWS_PB  136                     // ceil(20000/148): exactly 148 blocks
#define CPR      20                      // float4 chunks per row (C=80)
#define CHUNKS   (ROWS_PB * CPR)         // 2720
#define ITERS    6                       // ceil(2720/512)
#define FXSCALE  67108864.0              // 2^26
#define FXCLAMP  (1ll << 45)
#define BIAS     (1ll << 47)
#define CNT_UNIT (1ull << 56)
#define LOW_MASK ((1ull << 56) - 1ull)

__device__ unsigned long long g_acc        = 0ull;   // {count, biased fx}
__device__ int                g_first_fail = 0x7fffffff;

__device__ __forceinline__ float warp_max(float m) {
    #pragma unroll
    for (int off = 16; off; off >>= 1)
        m = fmaxf(m, __shfl_xor_sync(0xffffffffu, m, off));
    return m;
}
__device__ __forceinline__ float warp_sum(float s) {
    #pragma unroll
    for (int off = 16; off; off >>= 1)
        s += __shfl_xor_sync(0xffffffffu, s, off);
    return s;
}

__device__ __forceinline__ float row_max(const float* __restrict__ post,
                                         int row, int C) {
    float m = -3.4e38f;
    if (C == 80) {
        const float4* p = (const float4*)(post + (size_t)row * 80);
        #pragma unroll
        for (int i = 0; i < 20; i++) {
            float4 v = __ldg(p + i);
            m = fmaxf(m, fmaxf(fmaxf(v.x, v.y), fmaxf(v.z, v.w)));
        }
    } else {
        const float* p = post + (size_t)row * (size_t)C;
        for (int c = 0; c < C; c++) m = fmaxf(m, __ldg(p + c));
    }
    return m;
}

__global__ __launch_bounds__(THREADS)
void k_fused(const float* __restrict__ post,
             const float* __restrict__ boxes,
             int num, int rows_pb, int C, long long total_elems,
             float* __restrict__ out)
{
    const int lane = threadIdx.x & 31;
    const int wid  = threadIdx.x >> 5;
    __shared__ float cmax[ROWS_PB * (CPR + 1)];   // pad 21: conflict-free
    __shared__ float sh_red[THREADS / 32];
    __shared__ int   sh_mode;                     // 0 done/not-last, 1 max, 2 partial
    __shared__ int   sh_K;

    const int r0 = blockIdx.x * rows_pb;
    int rows_here = num - r0;
    if (rows_here > rows_pb) rows_here = rows_pb;
    if (rows_here < 0) rows_here = 0;

    float val = 0.0f;

    if (C == 80 && rows_pb == ROWS_PB) {
        const float4* p4 = (const float4*)post + (long long)r0 * CPR;
        // boxes load issued with phase-1 loads: single latency exposure
        float4 b = make_float4(0.f, 0.f, 0.f, 0.f);
        const bool has_row = (threadIdx.x < rows_here);
        if (has_row) b = __ldg((const float4*)boxes + (r0 + threadIdx.x));

        if (rows_here == ROWS_PB) {
            // ---- full block: batched loads, compile-time predicates ------
            float4 v[ITERS];
            #pragma unroll
            for (int i = 0; i < ITERS; i++) {
                int lc = i * THREADS + threadIdx.x;
                v[i] = (lc < CHUNKS) ? __ldg(p4 + lc)
                                     : make_float4(0.f, 0.f, 0.f, 0.f);
            }
            #pragma unroll
            for (int i = 0; i < ITERS; i++) {
                int lc = i * THREADS + threadIdx.x;
                if (lc < CHUNKS) {
                    float m3 = fmaxf(fmaxf(v[i].x, v[i].y), fmaxf(v[i].z, v[i].w));
                    int r = lc / CPR;
                    int c = lc - r * CPR;
                    cmax[r * (CPR + 1) + c] = m3;
                }
            }
        } else {
            const int nchunks = rows_here * CPR;
            for (int lc = threadIdx.x; lc < nchunks; lc += THREADS) {
                float4 v = __ldg(p4 + lc);
                float m3 = fmaxf(fmaxf(v.x, v.y), fmaxf(v.z, v.w));
                int r = lc / CPR;
                int c = lc - r * CPR;
                cmax[r * (CPR + 1) + c] = m3;
            }
        }
        __syncthreads();

        if (has_row) {
            const float* cm = &cmax[threadIdx.x * (CPR + 1)];
            // pairwise max tree (short dependency depth)
            float t0 = fmaxf(cm[0],  cm[1]),  t1 = fmaxf(cm[2],  cm[3]);
            float t2 = fmaxf(cm[4],  cm[5]),  t3 = fmaxf(cm[6],  cm[7]);
            float t4 = fmaxf(cm[8],  cm[9]),  t5 = fmaxf(cm[10], cm[11]);
            float t6 = fmaxf(cm[12], cm[13]), t7 = fmaxf(cm[14], cm[15]);
            float t8 = fmaxf(cm[16], cm[17]), t9 = fmaxf(cm[18], cm[19]);
            float u0 = fmaxf(t0, t1), u1 = fmaxf(t2, t3);
            float u2 = fmaxf(t4, t5), u3 = fmaxf(t6, t7);
            float u4 = fmaxf(t8, t9);
            float m  = fmaxf(fmaxf(fmaxf(u0, u1), fmaxf(u2, u3)), u4);
            val = m + ((b.x + b.y) + (b.z + b.w));
            if (!(m >= CONF_T)) atomicMin(&g_first_fail, r0 + threadIdx.x);
        }
    } else {
        // generic path (not hit for this shape)
        for (int row = r0 + threadIdx.x; row < r0 + rows_here; row += THREADS) {
            float m = row_max(post, row, C);
            float4 b = __ldg((const float4*)boxes + row);
            val += m + ((b.x + b.y) + (b.z + b.w));
            if (!(m >= CONF_T)) atomicMin(&g_first_fail, row);
        }
    }

    // ---- block reduction ---------------------------------------------------
    float s = warp_sum(val);
    if (lane == 0) sh_red[wid] = s;
    __syncthreads();
    if (threadIdx.x == 0) {
        float bs = 0.0f;
        #pragma unroll
        for (int i = 0; i < THREADS / 32; i++) bs += sh_red[i];

        long long fx = __double2ll_rn((double)bs * FXSCALE);
        if (fx >  FXCLAMP) fx =  FXCLAMP;   // counter-integrity guard only
        if (fx < -FXCLAMP) fx = -FXCLAMP;
        unsigned long long contrib = (unsigned long long)(fx + BIAS) + CNT_UNIT;

        unsigned long long old;
        asm volatile("atom.add.release.gpu.global.u64 %0, [%1], %2;"
                     : "=l"(old) : "l"(&g_acc), "l"(contrib) : "memory");

        sh_mode = 0;
        if ((old >> 56) == (unsigned long long)(gridDim.x - 1)) {
            // last block: final total already in-register
            asm volatile("fence.acquire.gpu;" ::: "memory");
            int ff = *(volatile int*)&g_first_fail;
            int K  = (ff < num) ? ff : num;
            if (K >= num) {
                unsigned long long fin = old + contrib;
                long long tot_fx = (long long)(fin & LOW_MASK)
                                 - (long long)gridDim.x * BIAS;
                out[0] = (float)((double)tot_fx / FXSCALE);
                // reset for next graph replay
                *(volatile unsigned long long*)&g_acc = 0ull;
                *(volatile int*)&g_first_fail = 0x7fffffff;
            } else if (K == 0) {
                sh_mode = 1;
            } else {
                sh_mode = 2; sh_K = K;
            }
        }
    }
    __syncthreads();
    const int mode = sh_mode;
    if (mode == 0) return;

    // ================= rare paths (last block only) =========================
    if (mode == 1) {
        // row 0 failed -> loss = max over all of post
        float m = -3.4e38f;
        const long long n4 = total_elems >> 2;
        const float4* p4 = (const float4*)post;
        for (long long i = threadIdx.x; i < n4; i += THREADS) {
            float4 v = p4[i];
            m = fmaxf(m, fmaxf(fmaxf(v.x, v.y), fmaxf(v.z, v.w)));
        }
        for (long long i = (n4 << 2) + threadIdx.x; i < total_elems; i += THREADS)
            m = fmaxf(m, post[i]);
        m = warp_max(m);
        if (lane == 0) sh_red[wid] = m;
        __syncthreads();
        if (threadIdx.x == 0) {
            #pragma unroll
            for (int i = 1; i < THREADS / 32; i++) m = fmaxf(m, sh_red[i]);
            out[0] = fmaxf(m, sh_red[0]);
            *(volatile unsigned long long*)&g_acc = 0ull;
            *(volatile int*)&g_first_fail = 0x7fffffff;
        }
    } else {
        // early break at K -> recompute sum over rows [0, K)
        const int K = sh_K;
        float s2 = 0.0f;
        for (int r = threadIdx.x; r < K; r += THREADS) {
            float m = row_max(post, r, C);
            float4 b = __ldg((const float4*)boxes + r);
            s2 += m + ((b.x + b.y) + (b.z + b.w));
        }
        s2 = warp_sum(s2);
        __syncthreads();
        if (lane == 0) sh_red[wid] = s2;
        __syncthreads();
        if (threadIdx.x == 0) {
            float t = 0.0f;
            #pragma unroll
            for (int i = 0; i < THREADS / 32; i++) t += sh_red[i];
            out[0] = t;
            *(volatile unsigned long long*)&g_acc = 0ull;
            *(volatile int*)&g_first_fail = 0x7fffffff;
        }
    }
}

extern "C" void kernel_launch(void* const* d_in, const int* in_sizes, int n_in,
                              void* d_out, int out_size)
{
    const float* post  = (const float*)d_in[0];   // [N, C] fp32
    const float* boxes = (const float*)d_in[1];   // [N, 4] fp32
    const long long total = (long long)in_sizes[0];
    const int N = in_sizes[1] / 4;
    const int C = (int)(total / N);

    int num = (int)((double)N * 0.02);
    if (num < 1) num = 1;
    if (num > N) num = N;

    int rows_pb, blocks;
    if (C == 80 && num <= ROWS_PB * 255) {
        rows_pb = ROWS_PB;                        // compile-time fast path
        blocks  = (num + rows_pb - 1) / rows_pb;  // 148 for num=20000
    } else {
        blocks  = (num + THREADS - 1) / THREADS;
        if (blocks > 255) blocks = 255;           // counter field limit
        rows_pb = (num + blocks - 1) / blocks;
    }
    k_fused<<<blocks, THREADS>>>(post, boxes, num, rows_pb, C, total,
                                 (float*)d_out);
}

// round 11
// speedup vs baseline: 1.3478x; 1.0193x over previous
#include <cuda_runtime.h>

// ---------------------------------------------------------------------------
// yolo_detect_target — one kernel, one atomic carries {counter | failflags |
// biased fixed-point sum}. Last block decides the common path entirely from
// the atomic return value (no dependent global reads). 2 blocks/SM overlap
// load-drain with reduce. Rare paths (early conf break, row-0 fail -> global
// max) read g_first_fail and run in the last block only.
// Field layout of g_acc (u64):
//   bits [ 0,40) : sum of (fx + BIAS), fx = round(block_sum * 2^20)
//   bits [40,50) : # blocks with a conf failure (leader adds 1)
//   bits [50,60) : # completed blocks
// ---------------------------------------------------------------------------

#define CONF_T    0.25f
#define THREADS   256
#define ROWS_PB   68
#define CPR       20                    // float4 chunks per row (C=80)
#define CHUNKS    (ROWS_PB * CPR)       // 1360
#define ITERS     6                     // ceil(1360/256)
#define FXSCALE   1048576.0             // 2^20
#define FXCLAMP   (1ll << 30)
#define BIAS      (1ll << 31)
#define FAIL_UNIT (1ull << 40)
#define CNT_SHIFT 50
#define CNT_UNIT  (1ull << 50)
#define SUM_MASK  ((1ull << 40) - 1ull)
#define FAIL_MASK 0x3ffull
#define MAX_BLOCKS 1023                 // 10-bit counter / fail fields

__device__ unsigned long long g_acc        = 0ull;
__device__ int                g_first_fail = 0x7fffffff;

__device__ __forceinline__ float warp_max(float m) {
    #pragma unroll
    for (int off = 16; off; off >>= 1)
        m = fmaxf(m, __shfl_xor_sync(0xffffffffu, m, off));
    return m;
}
__device__ __forceinline__ float warp_sum(float s) {
    #pragma unroll
    for (int off = 16; off; off >>= 1)
        s += __shfl_xor_sync(0xffffffffu, s, off);
    return s;
}

__device__ __forceinline__ float row_max(const float* __restrict__ post,
                                         int row, int C) {
    float m = -3.4e38f;
    if (C == 80) {
        const float4* p = (const float4*)(post + (size_t)row * 80);
        #pragma unroll
        for (int i = 0; i < 20; i++) {
            float4 v = __ldg(p + i);
            m = fmaxf(m, fmaxf(fmaxf(v.x, v.y), fmaxf(v.z, v.w)));
        }
    } else {
        const float* p = post + (size_t)row * (size_t)C;
        for (int c = 0; c < C; c++) m = fmaxf(m, __ldg(p + c));
    }
    return m;
}

__global__ __launch_bounds__(THREADS)
void k_fused(const float* __restrict__ post,
             const float* __restrict__ boxes,
             int num, int rows_pb, int C, long long total_elems,
             float* __restrict__ out)
{
    const int lane = threadIdx.x & 31;
    const int wid  = threadIdx.x >> 5;
    __shared__ float cmax[ROWS_PB * (CPR + 1)];   // pad 21: conflict-free
    __shared__ float sh_red[THREADS / 32];
    __shared__ int   sh_fail;
    __shared__ int   sh_mode;                     // 0 done, 1 global max, 2 partial
    __shared__ int   sh_K;

    if (threadIdx.x == 0) sh_fail = 0;

    const int r0 = blockIdx.x * rows_pb;
    int rows_here = num - r0;
    if (rows_here > rows_pb) rows_here = rows_pb;
    if (rows_here < 0) rows_here = 0;

    float val = 0.0f;

    if (C == 80 && rows_pb == ROWS_PB) {
        const float4* p4 = (const float4*)post + (long long)r0 * CPR;
        float4 b = make_float4(0.f, 0.f, 0.f, 0.f);
        const bool has_row = (threadIdx.x < rows_here);
        if (has_row) b = __ldg((const float4*)boxes + (r0 + threadIdx.x));

        if (rows_here == ROWS_PB) {
            // ---- full block: batched loads (compile-time predicates) -----
            float4 v[ITERS];
            #pragma unroll
            for (int i = 0; i < ITERS; i++) {
                int lc = i * THREADS + threadIdx.x;
                v[i] = (lc < CHUNKS) ? __ldg(p4 + lc)
                                     : make_float4(0.f, 0.f, 0.f, 0.f);
            }
            #pragma unroll
            for (int i = 0; i < ITERS; i++) {
                int lc = i * THREADS + threadIdx.x;
                if (lc < CHUNKS) {
                    float m3 = fmaxf(fmaxf(v[i].x, v[i].y), fmaxf(v[i].z, v[i].w));
                    int r = lc / CPR;
                    int c = lc - r * CPR;
                    cmax[r * (CPR + 1) + c] = m3;
                }
            }
        } else {
            const int nchunks = rows_here * CPR;
            for (int lc = threadIdx.x; lc < nchunks; lc += THREADS) {
                float4 v = __ldg(p4 + lc);
                float m3 = fmaxf(fmaxf(v.x, v.y), fmaxf(v.z, v.w));
                int r = lc / CPR;
                int c = lc - r * CPR;
                cmax[r * (CPR + 1) + c] = m3;
            }
        }
        __syncthreads();   // also orders sh_fail=0 before any failure write

        if (has_row) {
            const float* cm = &cmax[threadIdx.x * (CPR + 1)];
            float t0 = fmaxf(cm[0],  cm[1]),  t1 = fmaxf(cm[2],  cm[3]);
            float t2 = fmaxf(cm[4],  cm[5]),  t3 = fmaxf(cm[6],  cm[7]);
            float t4 = fmaxf(cm[8],  cm[9]),  t5 = fmaxf(cm[10], cm[11]);
            float t6 = fmaxf(cm[12], cm[13]), t7 = fmaxf(cm[14], cm[15]);
            float t8 = fmaxf(cm[16], cm[17]), t9 = fmaxf(cm[18], cm[19]);
            float u0 = fmaxf(t0, t1), u1 = fmaxf(t2, t3);
            float u2 = fmaxf(t4, t5), u3 = fmaxf(t6, t7);
            float u4 = fmaxf(t8, t9);
            float m  = fmaxf(fmaxf(fmaxf(u0, u1), fmaxf(u2, u3)), u4);
            val = m + ((b.x + b.y) + (b.z + b.w));
            if (!(m >= CONF_T)) {
                sh_fail = 1;
                atomicMin(&g_first_fail, r0 + threadIdx.x);
            }
        }
    } else {
        // generic path (not hit for this shape)
        __syncthreads();   // order sh_fail init
        for (int row = r0 + threadIdx.x; row < r0 + rows_here; row += THREADS) {
            float m = row_max(post, row, C);
            float4 b = __ldg((const float4*)boxes + row);
            val += m + ((b.x + b.y) + (b.z + b.w));
            if (!(m >= CONF_T)) {
                sh_fail = 1;
                atomicMin(&g_first_fail, row);
            }
        }
    }

    // ---- block reduction ---------------------------------------------------
    float s = warp_sum(val);
    if (lane == 0) sh_red[wid] = s;
    __syncthreads();
    if (threadIdx.x == 0) {
        float bs = 0.0f;
        #pragma unroll
        for (int i = 0; i < THREADS / 32; i++) bs += sh_red[i];

        long long fx = __double2ll_rn((double)bs * FXSCALE);
        if (fx >  FXCLAMP) fx =  FXCLAMP;   // field-integrity guard only
        if (fx < -FXCLAMP) fx = -FXCLAMP;
        unsigned long long contrib = (unsigned long long)(fx + BIAS) + CNT_UNIT;
        if (sh_fail) contrib += FAIL_UNIT;

        unsigned long long old;
        asm volatile("atom.add.release.gpu.global.u64 %0, [%1], %2;"
                     : "=l"(old) : "l"(&g_acc), "l"(contrib) : "memory");

        sh_mode = 0;
        if ((old >> CNT_SHIFT) == (unsigned long long)(gridDim.x - 1)) {
            unsigned long long fin = old + contrib;
            if (((fin >> 40) & FAIL_MASK) == 0ull) {
                // common case: no failures anywhere -> answer in-register
                long long tot_fx = (long long)(fin & SUM_MASK)
                                 - (long long)gridDim.x * BIAS;
                out[0] = (float)((double)tot_fx / FXSCALE);
                *(volatile unsigned long long*)&g_acc = 0ull;
            } else {
                asm volatile("fence.acquire.gpu;" ::: "memory");
                int ff = *(volatile int*)&g_first_fail;
                int K  = (ff < num) ? ff : num;
                if (K == 0)      sh_mode = 1;
                else             { sh_mode = 2; sh_K = K; }
            }
        }
    }
    __syncthreads();
    const int mode = sh_mode;
    if (mode == 0) return;

    // ================= rare paths (last block only) =========================
    if (mode == 1) {
        // row 0 failed -> loss = max over all of post
        float m = -3.4e38f;
        const long long n4 = total_elems >> 2;
        const float4* p4 = (const float4*)post;
        for (long long i = threadIdx.x; i < n4; i += THREADS) {
            float4 v = p4[i];
            m = fmaxf(m, fmaxf(fmaxf(v.x, v.y), fmaxf(v.z, v.w)));
        }
        for (long long i = (n4 << 2) + threadIdx.x; i < total_elems; i += THREADS)
            m = fmaxf(m, post[i]);
        m = warp_max(m);
        if (lane == 0) sh_red[wid] = m;
        __syncthreads();
        if (threadIdx.x == 0) {
            float r = sh_red[0];
            #pragma unroll
            for (int i = 1; i < THREADS / 32; i++) r = fmaxf(r, sh_red[i]);
            out[0] = r;
            *(volatile unsigned long long*)&g_acc = 0ull;
            *(volatile int*)&g_first_fail = 0x7fffffff;
        }
    } else {
        // early break at K (>=1) -> recompute sum over rows [0, K)
        const int K = sh_K;
        float s2 = 0.0f;
        for (int r = threadIdx.x; r < K; r += THREADS) {
            float m = row_max(post, r, C);
            float4 b = __ldg((const float4*)boxes + r);
            s2 += m + ((b.x + b.y) + (b.z + b.w));
        }
        s2 = warp_sum(s2);
        __syncthreads();
        if (lane == 0) sh_red[wid] = s2;
        __syncthreads();
        if (threadIdx.x == 0) {
            float t = 0.0f;
            #pragma unroll
            for (int i = 0; i < THREADS / 32; i++) t += sh_red[i];
            out[0] = t;
            *(volatile unsigned long long*)&g_acc = 0ull;
            *(volatile int*)&g_first_fail = 0x7fffffff;
        }
    }
}

extern "C" void kernel_launch(void* const* d_in, const int* in_sizes, int n_in,
                              void* d_out, int out_size)
{
    const float* post  = (const float*)d_in[0];   // [N, C] fp32
    const float* boxes = (const float*)d_in[1];   // [N, 4] fp32
    const long long total = (long long)in_sizes[0];
    const int N = in_sizes[1] / 4;
    const int C = (int)(total / N);

    int num = (int)((double)N * 0.02);
    if (num < 1) num = 1;
    if (num > N) num = N;

    int rows_pb, blocks;
    if (C == 80 && num <= ROWS_PB * MAX_BLOCKS) {
        rows_pb = ROWS_PB;                          // compile-time fast path
        blocks  = (num + rows_pb - 1) / rows_pb;    // 295 for num=20000
    } else {
        blocks  = (num + THREADS - 1) / THREADS;
        if (blocks > MAX_BLOCKS) blocks = MAX_BLOCKS;
        rows_pb = (num + blocks - 1) / blocks;
    }
    k_fused<<<blocks, THREADS>>>(post, boxes, num, rows_pb, C, total,
                                 (float*)d_out);
}